// round 7
// baseline (speedup 1.0000x reference)
#include <cuda_runtime.h>
#include <math.h>

#define NN   30000
#define E1   400000
#define C1N  15000
#define E2N  100000
#define C2N  7500
#define NBAT 16

typedef unsigned long long u64;

// ---------------- scratch (__device__ globals; no dynamic alloc) ----------------
__device__ int      g_cnt_dst1[NN];
__device__ int      g_off1[NN];
__device__ int      g_cur1[NN];
__device__ float4   g_ep1[E1];      // per-edge payload: {src, ea0, ea1, ea2}
__device__ int      g_cnt_c1[C1N];
__device__ int      g_cnt_dst2[C1N];
__device__ int      g_off2[C1N];
__device__ int      g_cur2[C1N];
__device__ float4   g_ep2[E2N];     // per-edge payload: {src, cart0, cart1, cart2}
__device__ float    g_possum[C1N * 3];
__device__ int      g_batchp[C1N];
__device__ unsigned g_xp_u[C1N * 32];
__device__ float    g_W1p[162 * 32];
__device__ unsigned g_absmax;
__device__ float    g_A2[C1N * 864];
__device__ float    g_W2p[864 * 64];
__device__ unsigned g_x3_u[C2N * 64];
__device__ int      g_batch2[C2N];
__device__ float    g_gsum[NBAT * 64];
__device__ int      g_cntb[NBAT];

// packed f32x2 helpers (FFMA2 path — PTX-only, doubles fp32 FMA throughput)
__device__ __forceinline__ u64 pk(float lo, float hi) {
    u64 r; asm("mov.b64 %0,{%1,%2};" : "=l"(r) : "f"(lo), "f"(hi)); return r;
}
__device__ __forceinline__ void upk(u64 v, float& lo, float& hi) {
    asm("mov.b64 {%0,%1},%2;" : "=f"(lo), "=f"(hi) : "l"(v));
}
__device__ __forceinline__ u64 fma2(u64 a, u64 b, u64 c) {
    u64 d; asm("fma.rn.f32x2 %0,%1,%2,%3;" : "=l"(d) : "l"(a), "l"(b), "l"(c)); return d;
}

// order-preserving float <-> uint so atomicMax works; 0u == "empty" decodes to 0.0f
__device__ __forceinline__ unsigned fenc(float f) {
    unsigned u = __float_as_uint(f);
    return (u & 0x80000000u) ? ~u : (u | 0x80000000u);
}
__device__ __forceinline__ float fdec(unsigned u) {
    if (u == 0u) return 0.f;
    return (u & 0x80000000u) ? __uint_as_float(u & 0x7FFFFFFFu) : __uint_as_float(~u);
}
__device__ __forceinline__ float elu_f(float x) {
    return x > 0.f ? x : (expf(x) - 1.f);
}

// ---------------- init: zero scratch + repack fused weights ----------------
__global__ void k_init(const float* __restrict__ w1b, const float* __restrict__ b1b,
                       const float* __restrict__ root1,
                       const float* __restrict__ w2b, const float* __restrict__ b2b,
                       const float* __restrict__ root2) {
    int t = blockIdx.x * blockDim.x + threadIdx.x;
    int S = gridDim.x * blockDim.x;
    for (int i = t; i < C1N * 32; i += S) g_xp_u[i] = 0u;
    for (int i = t; i < C2N * 64; i += S) g_x3_u[i] = 0u;
    for (int i = t; i < C1N * 3;  i += S) g_possum[i] = 0.f;
    for (int i = t; i < NN;       i += S) g_cnt_dst1[i] = 0;
    for (int i = t; i < C1N;      i += S) { g_cnt_c1[i] = 0; g_cnt_dst2[i] = 0; g_batchp[i] = 0; }
    for (int i = t; i < C2N;      i += S) g_batch2[i] = 0;
    for (int i = t; i < NBAT * 64;i += S) g_gsum[i] = 0.f;
    for (int i = t; i < NBAT;     i += S) g_cntb[i] = 0;
    if (t == 0) g_absmax = 0u;
    // W1p[j,o]: j=i*26+k (i<6,k<26): k<25 -> w1b[k, i*32+o], k==25 -> b1b[i*32+o];
    //           j in [156,162): root1[j-156, o]
    for (int idx = t; idx < 162 * 32; idx += S) {
        int j = idx >> 5, o = idx & 31;
        float v;
        if (j < 156) {
            int i = j / 26, k = j % 26;
            v = (k < 25) ? w1b[k * 192 + i * 32 + o] : b1b[i * 32 + o];
        } else {
            v = root1[(j - 156) * 32 + o];
        }
        g_W1p[idx] = v;
    }
    // W2p[j,o]: j=k*32+i (k<26,i<32): k<25 -> w2b[k, i*64+o], k==25 -> b2b[i*64+o];
    //           j in [832,864): root2[j-832, o]
    for (int idx = t; idx < 864 * 64; idx += S) {
        int j = idx >> 6, o = idx & 63;
        float v;
        if (j < 832) {
            int k = j >> 5, i = j & 31;
            v = (k < 25) ? w2b[k * 2048 + i * 64 + o] : b2b[i * 64 + o];
        } else {
            v = root2[(j - 832) * 64 + o];
        }
        g_W2p[idx] = v;
    }
}

// ---------------- degree counts + pos-sum + batchp ----------------
__global__ void k_count(const int* __restrict__ eidx, const int* __restrict__ eidx2,
                        const int* __restrict__ cl1, const int* __restrict__ batch,
                        const float* __restrict__ pos) {
    int t = blockIdx.x * blockDim.x + threadIdx.x;
    int S = gridDim.x * blockDim.x;
    for (int e = t; e < E1;  e += S) atomicAdd(&g_cnt_dst1[eidx[E1 + e]], 1);
    for (int e = t; e < E2N; e += S) atomicAdd(&g_cnt_dst2[eidx2[E2N + e]], 1);
    for (int n = t; n < NN;  n += S) {
        int c = cl1[n];
        atomicAdd(&g_cnt_c1[c], 1);
        atomicAdd(&g_possum[c * 3 + 0], pos[n * 3 + 0]);
        atomicAdd(&g_possum[c * 3 + 1], pos[n * 3 + 1]);
        atomicAdd(&g_possum[c * 3 + 2], pos[n * 3 + 2]);
        atomicMax(&g_batchp[c], batch[n]);
    }
}

// ---------------- scan (2 blocks) + pos-mean/batch2 (block 2), one launch ----------------
__device__ void scan_one(const int* __restrict__ cnt, int* __restrict__ off,
                         int* __restrict__ cur, int n) {
    __shared__ int wsum[32];
    int t = threadIdx.x;
    int lane = t & 31, w = t >> 5;
    int chunk = (n + 1023) / 1024;
    int lo = t * chunk, hi = min(lo + chunk, n);
    int s = 0;
    for (int i = lo; i < hi; i++) s += cnt[i];
    int v = s;
#pragma unroll
    for (int d = 1; d < 32; d <<= 1) {
        int u = __shfl_up_sync(0xffffffffu, v, d);
        if (lane >= d) v += u;
    }
    if (lane == 31) wsum[w] = v;
    __syncthreads();
    if (w == 0) {
        int x = wsum[lane];
#pragma unroll
        for (int d = 1; d < 32; d <<= 1) {
            int u = __shfl_up_sync(0xffffffffu, x, d);
            if (lane >= d) x += u;
        }
        wsum[lane] = x;
    }
    __syncthreads();
    int run = (w ? wsum[w - 1] : 0) + (v - s);
    for (int i = lo; i < hi; i++) { off[i] = run; cur[i] = run; run += cnt[i]; }
}
__global__ void k_scan2(const int* __restrict__ cl2) {
    if (blockIdx.x == 0) scan_one(g_cnt_dst1, g_off1, g_cur1, NN);
    else if (blockIdx.x == 1) scan_one(g_cnt_dst2, g_off2, g_cur2, C1N);
    else {
        // possum -> mean (in place) + batch2 = segmax(batchp by cl2)
        for (int c = threadIdx.x; c < C1N; c += blockDim.x) {
            float inv = 1.f / (float)max(g_cnt_c1[c], 1);
            g_possum[c * 3 + 0] *= inv;
            g_possum[c * 3 + 1] *= inv;
            g_possum[c * 3 + 2] *= inv;
            atomicMax(&g_batch2[cl2[c]], g_batchp[c]);
        }
    }
}

// ---------------- fill CSR edge payloads, 4-way software pipelined ----------------
__global__ void k_fill(const int* __restrict__ eidx, const float* __restrict__ ea,
                       const int* __restrict__ eidx2) {
    int t = blockIdx.x * blockDim.x + threadIdx.x;
    int S = gridDim.x * blockDim.x;
    // level 1: batches of 4 independent atomic chains (MLP=4)
    for (int base = t * 4; base < E1; base += S * 4) {
        if (base + 3 < E1) {
            int s0 = eidx[base + 0], s1 = eidx[base + 1], s2 = eidx[base + 2], s3 = eidx[base + 3];
            int d0 = eidx[E1 + base + 0], d1 = eidx[E1 + base + 1];
            int d2 = eidx[E1 + base + 2], d3 = eidx[E1 + base + 3];
            float a00 = ea[(base+0)*3], a01 = ea[(base+0)*3+1], a02 = ea[(base+0)*3+2];
            float a10 = ea[(base+1)*3], a11 = ea[(base+1)*3+1], a12 = ea[(base+1)*3+2];
            float a20 = ea[(base+2)*3], a21 = ea[(base+2)*3+1], a22 = ea[(base+2)*3+2];
            float a30 = ea[(base+3)*3], a31 = ea[(base+3)*3+1], a32 = ea[(base+3)*3+2];
            int p0 = atomicAdd(&g_cur1[d0], 1);
            int p1 = atomicAdd(&g_cur1[d1], 1);
            int p2 = atomicAdd(&g_cur1[d2], 1);
            int p3 = atomicAdd(&g_cur1[d3], 1);
            g_ep1[p0] = make_float4(__int_as_float(s0), a00, a01, a02);
            g_ep1[p1] = make_float4(__int_as_float(s1), a10, a11, a12);
            g_ep1[p2] = make_float4(__int_as_float(s2), a20, a21, a22);
            g_ep1[p3] = make_float4(__int_as_float(s3), a30, a31, a32);
        } else {
            for (int e = base; e < E1; e++) {
                int s = eidx[e], d = eidx[E1 + e];
                int p = atomicAdd(&g_cur1[d], 1);
                g_ep1[p] = make_float4(__int_as_float(s), ea[e*3], ea[e*3+1], ea[e*3+2]);
            }
        }
    }
    float m = 0.f;
    for (int base = t * 2; base < E2N; base += S * 2) {
        int cnt = min(2, E2N - base);
        int sA[2], dA[2], pA[2];
        float c0[2], c1[2], c2[2];
        for (int j = 0; j < cnt; j++) { sA[j] = eidx2[base + j]; dA[j] = eidx2[E2N + base + j]; }
        for (int j = 0; j < cnt; j++) {
            c0[j] = g_possum[sA[j]*3+0] - g_possum[dA[j]*3+0];
            c1[j] = g_possum[sA[j]*3+1] - g_possum[dA[j]*3+1];
            c2[j] = g_possum[sA[j]*3+2] - g_possum[dA[j]*3+2];
        }
        for (int j = 0; j < cnt; j++) pA[j] = atomicAdd(&g_cur2[dA[j]], 1);
        for (int j = 0; j < cnt; j++) {
            g_ep2[pA[j]] = make_float4(__int_as_float(sA[j]), c0[j], c1[j], c2[j]);
            m = fmaxf(m, fmaxf(fabsf(c0[j]), fmaxf(fabsf(c1[j]), fabsf(c2[j]))));
        }
    }
#pragma unroll
    for (int o = 16; o; o >>= 1) m = fmaxf(m, __shfl_xor_sync(0xffffffffu, m, o));
    if ((threadIdx.x & 31) == 0 && m > 0.f) atomicMax(&g_absmax, __float_as_uint(m));
}

// ---------------- conv1 + gemm1 + elu + pool1-max FUSED: one warp per dst node ----------------
__global__ void k_conv1(const float* __restrict__ x,
                        const float* __restrict__ w1a, const float* __restrict__ b1a,
                        const float* __restrict__ bias1, const int* __restrict__ cl1) {
    int wg = (blockIdx.x * blockDim.x + threadIdx.x) >> 5;
    int lane = threadIdx.x & 31;
    if (wg >= NN) return;
    int n = wg;
    float wa0 = 0.f, wa1 = 0.f, wa2 = 0.f, ba = 0.f;
    if (lane < 25) { wa0 = w1a[lane]; wa1 = w1a[25 + lane]; wa2 = w1a[50 + lane]; ba = b1a[lane]; }
    u64 acc0 = 0, acc1 = 0, acc2 = 0;
    int off = g_off1[n], deg = g_cnt_dst1[n];
    const float4* ep = &g_ep1[off];
    for (int q = 0; q < deg; q++) {
        float4 p = ep[q];                       // uniform broadcast load
        int s = __float_as_int(p.x);
        float h;
        if (lane < 25) {
            h = fmaf(p.w, wa2, fmaf(p.z, wa1, fmaf(p.y, wa0, ba)));
            h = fmaxf(h, 0.f);
        } else {
            h = (lane == 25) ? 1.f : 0.f;
        }
        u64 hh = pk(h, h);
        const u64* xr = (const u64*)(x + s * 6);  // uniform broadcast, 8B-aligned
        acc0 = fma2(xr[0], hh, acc0);
        acc1 = fma2(xr[1], hh, acc1);
        acc2 = fma2(xr[2], hh, acc2);
    }
    float inv = 1.f / (float)max(deg, 1);
    float sv[6];
    upk(acc0, sv[0], sv[1]); upk(acc1, sv[2], sv[3]); upk(acc2, sv[4], sv[5]);
#pragma unroll
    for (int i = 0; i < 6; i++) sv[i] *= inv;
    // fused GEMM row: out[o=lane] = sum_{i,k} S[i][k] * W1p[(i*26+k)*32+o] + self + bias
    float o_acc = bias1[lane];
#pragma unroll
    for (int i = 0; i < 6; i++) {
        float si = sv[i];
#pragma unroll
        for (int k = 0; k < 26; k++) {
            float av = __shfl_sync(0xffffffffu, si, k);
            o_acc = fmaf(av, g_W1p[(i * 26 + k) * 32 + lane], o_acc);
        }
    }
    const u64* xs = (const u64*)(x + n * 6);
    float x0, x1, x2, x3, x4, x5;
    upk(xs[0], x0, x1); upk(xs[1], x2, x3); upk(xs[2], x4, x5);
    o_acc = fmaf(x0, g_W1p[156 * 32 + lane], o_acc);
    o_acc = fmaf(x1, g_W1p[157 * 32 + lane], o_acc);
    o_acc = fmaf(x2, g_W1p[158 * 32 + lane], o_acc);
    o_acc = fmaf(x3, g_W1p[159 * 32 + lane], o_acc);
    o_acc = fmaf(x4, g_W1p[160 * 32 + lane], o_acc);
    o_acc = fmaf(x5, g_W1p[161 * 32 + lane], o_acc);
    float v = elu_f(o_acc);
    atomicMax(&g_xp_u[cl1[n] * 32 + lane], fenc(v));
}

// ---------------- conv2 edge accumulation: one warp per destination cluster ----------------
// reads pooled features directly from g_xp_u with inline decode (no k_dec pass)
__global__ void k_conv2(const float* __restrict__ w2a, const float* __restrict__ b2a) {
    int wg = (blockIdx.x * blockDim.x + threadIdx.x) >> 5;
    int lane = threadIdx.x & 31;
    if (wg >= C1N) return;
    int c = wg;
    float wa0 = 0.f, wa1 = 0.f, wa2 = 0.f, ba = 0.f;
    if (lane < 25) { wa0 = w2a[lane]; wa1 = w2a[25 + lane]; wa2 = w2a[50 + lane]; ba = b2a[lane]; }
    float scale = 0.5f / __uint_as_float(g_absmax);
    float acc[26];
#pragma unroll
    for (int k = 0; k < 26; k++) acc[k] = 0.f;
    int off = g_off2[c], deg = g_cnt_dst2[c];
    const float4* ep = &g_ep2[off];
    for (int q = 0; q < deg; q++) {
        float4 p = ep[q];                       // uniform broadcast load
        int s = __float_as_int(p.x);
        float h;
        if (lane < 25) {
            float c0 = fmaf(p.y, scale, 0.5f);
            float c1 = fmaf(p.z, scale, 0.5f);
            float c2 = fmaf(p.w, scale, 0.5f);
            h = fmaf(c2, wa2, fmaf(c1, wa1, fmaf(c0, wa0, ba)));
            h = fmaxf(h, 0.f);
        } else {
            h = (lane == 25) ? 1.f : 0.f;
        }
        float xv = fdec(g_xp_u[s * 32 + lane]);  // coalesced 128B + inline decode
#pragma unroll
        for (int k = 0; k < 26; k++)
            acc[k] = fmaf(xv, __shfl_sync(0xffffffffu, h, k), acc[k]);
    }
    float inv = 1.f / (float)max(deg, 1);
    float* Arow = &g_A2[c * 864];
#pragma unroll
    for (int k = 0; k < 26; k++) Arow[k * 32 + lane] = acc[k] * inv;
    Arow[832 + lane] = fdec(g_xp_u[c * 32 + lane]);
}

// ---------------- GEMM2 [C1,864]@[864,64]: block-tiled smem, FFMA2, fused elu+pool ---------
#define MB 64
#define KC 48
__global__ void k_gemm2(const float* __restrict__ bias2, const int* __restrict__ cl2) {
    __shared__ u64   sA[MB][KC];   // duplicated f32x2 pairs: 64*48*8 = 24.5 KB
    __shared__ float sW[KC][64];   // 48*64*4 = 12 KB
    int tid = threadIdx.x;
    int warp = tid >> 5, lane = tid & 31;
    int row0 = blockIdx.x * MB;
    u64 acc[8];
#pragma unroll
    for (int r = 0; r < 8; r++) acc[r] = 0;
    for (int kc = 0; kc < 864; kc += KC) {
        for (int i = tid; i < MB * KC; i += 256) {
            int r = i / KC, k = i - r * KC;
            int rr = min(row0 + r, C1N - 1);
            float v = g_A2[rr * 864 + kc + k];
            sA[r][k] = pk(v, v);
        }
        for (int i = tid; i < KC * 64; i += 256)
            sW[i >> 6][i & 63] = g_W2p[(kc + (i >> 6)) * 64 + (i & 63)];
        __syncthreads();
        int rb = warp * 8;
#pragma unroll 4
        for (int k = 0; k < KC; k++) {
            u64 w = *(const u64*)&sW[k][2 * lane];
#pragma unroll
            for (int r = 0; r < 8; r++)
                acc[r] = fma2(sA[rb + r][k], w, acc[r]);
        }
        __syncthreads();
    }
    float b0 = bias2[2 * lane], b1 = bias2[2 * lane + 1];
#pragma unroll
    for (int r = 0; r < 8; r++) {
        int n = row0 + warp * 8 + r;
        if (n < C1N) {
            float a0, a1;
            upk(acc[r], a0, a1);
            float v0 = elu_f(a0 + b0);
            float v1 = elu_f(a1 + b1);
            int c2 = cl2[n];
            atomicMax(&g_x3_u[c2 * 64 + 2 * lane + 0], fenc(v0));
            atomicMax(&g_x3_u[c2 * 64 + 2 * lane + 1], fenc(v1));
        }
    }
}

// ---------------- pool2 -> per-batch sums via shared staging ----------------
__global__ void k_pool2() {
    __shared__ float sh[NBAT * 64];
    __shared__ int scnt[NBAT];
    int t = threadIdx.x;
    for (int i = t; i < NBAT * 64; i += blockDim.x) sh[i] = 0.f;
    if (t < NBAT) scnt[t] = 0;
    __syncthreads();
    int g = blockIdx.x * blockDim.x + t;
    int S = gridDim.x * blockDim.x;
    for (int idx = g; idx < C2N * 64; idx += S) {
        float v = fdec(g_x3_u[idx]);
        int c2 = idx >> 6, o = idx & 63;
        int b = g_batch2[c2];
        atomicAdd(&sh[b * 64 + o], v);
        if (o == 0) atomicAdd(&scnt[b], 1);
    }
    __syncthreads();
    for (int i = t; i < NBAT * 64; i += blockDim.x)
        if (sh[i] != 0.f) atomicAdd(&g_gsum[i], sh[i]);
    if (t < NBAT && scnt[t]) atomicAdd(&g_cntb[t], scnt[t]);
}

// ---------------- head: mean -> fc1+elu -> fc2 -> log_softmax ----------------
__global__ void k_head(const float* __restrict__ fc1w, const float* __restrict__ fc1b,
                       const float* __restrict__ fc2w, const float* __restrict__ fc2b,
                       float* __restrict__ out) {
    __shared__ float sg[16 * 64];
    __shared__ float sh[16 * 128];
    __shared__ float sl[16 * 10];
    int t = threadIdx.x;
    for (int i = t; i < 16 * 64; i += 256) {
        int b = i >> 6;
        sg[i] = g_gsum[i] / (float)max(g_cntb[b], 1);
    }
    __syncthreads();
    for (int i = t; i < 16 * 128; i += 256) {
        int b = i >> 7, j = i & 127;
        float a = fc1b[j];
        for (int q = 0; q < 64; q++) a = fmaf(sg[b * 64 + q], fc1w[q * 128 + j], a);
        sh[i] = elu_f(a);
    }
    __syncthreads();
    for (int i = t; i < 160; i += 256) {
        int b = i / 10, j = i % 10;
        float a = fc2b[j];
        for (int q = 0; q < 128; q++) a = fmaf(sh[b * 128 + q], fc2w[q * 10 + j], a);
        sl[i] = a;
    }
    __syncthreads();
    if (t < 16) {
        float m = -1e30f;
        for (int j = 0; j < 10; j++) m = fmaxf(m, sl[t * 10 + j]);
        float s = 0.f;
        for (int j = 0; j < 10; j++) s += expf(sl[t * 10 + j] - m);
        float lse = logf(s);
        for (int j = 0; j < 10; j++) out[t * 10 + j] = sl[t * 10 + j] - m - lse;
    }
}

// ---------------- host launch ----------------
extern "C" void kernel_launch(void* const* d_in, const int* in_sizes, int n_in,
                              void* d_out, int out_size) {
    const float *x = 0, *ea = 0, *pos = 0, *w1a = 0, *b1a = 0, *w1b = 0, *b1b = 0,
                *root1 = 0, *bias1 = 0, *w2a = 0, *b2a = 0, *w2b = 0, *b2b = 0,
                *root2 = 0, *bias2 = 0, *fc1w = 0, *fc1b = 0, *fc2w = 0, *fc2b = 0;
    const int *eidx = 0, *batch = 0, *cl1 = 0, *eidx2 = 0, *cl2 = 0;
    int c75 = 0, c25 = 0, c192 = 0, c2048 = 0, c30000 = 0;
    for (int i = 0; i < n_in; i++) {
        const void* p = d_in[i];
        switch (in_sizes[i]) {
            case 180000:  x = (const float*)p; break;
            case 1200000: ea = (const float*)p; break;
            case 90000:   pos = (const float*)p; break;
            case 800000:  eidx = (const int*)p; break;
            case 30000:   if (c30000++ == 0) batch = (const int*)p; else cl1 = (const int*)p; break;
            case 200000:  eidx2 = (const int*)p; break;
            case 15000:   cl2 = (const int*)p; break;
            case 75:      if (c75++ == 0) w1a = (const float*)p; else w2a = (const float*)p; break;
            case 25:      if (c25++ == 0) b1a = (const float*)p; else b2a = (const float*)p; break;
            case 4800:    w1b = (const float*)p; break;
            case 192:     if (c192++ == 0) b1b = (const float*)p; else root1 = (const float*)p; break;
            case 32:      bias1 = (const float*)p; break;
            case 51200:   w2b = (const float*)p; break;
            case 2048:    if (c2048++ == 0) b2b = (const float*)p; else root2 = (const float*)p; break;
            case 64:      bias2 = (const float*)p; break;
            case 8192:    fc1w = (const float*)p; break;
            case 128:     fc1b = (const float*)p; break;
            case 1280:    fc2w = (const float*)p; break;
            case 10:      fc2b = (const float*)p; break;
            default: break;
        }
    }
    float* out = (float*)d_out;
    (void)out_size;

    k_init<<<256, 256>>>(w1b, b1b, root1, w2b, b2b, root2);
    k_count<<<512, 256>>>(eidx, eidx2, cl1, batch, pos);
    k_scan2<<<3, 1024>>>(cl2);
    k_fill<<<512, 256>>>(eidx, ea, eidx2);
    k_conv1<<<(NN * 32 + 255) / 256, 256>>>(x, w1a, b1a, bias1, cl1);
    k_conv2<<<(C1N * 32 + 255) / 256, 256>>>(w2a, b2a);
    k_gemm2<<<(C1N + MB - 1) / MB, 256>>>(bias2, cl2);
    k_pool2<<<120, 256>>>();
    k_head<<<1, 256>>>(fc1w, fc1b, fc2w, fc2b, out);
}

// round 8
// speedup vs baseline: 1.0993x; 1.0993x over previous
#include <cuda_runtime.h>
#include <math.h>

#define NN   30000
#define E1   400000
#define C1N  15000
#define E2N  100000
#define C2N  7500
#define NBAT 16
#define NB   592      // 4 blocks/SM on 148 SMs; <= residency on GB300's 152 SMs

typedef unsigned long long u64;

// ---------------- scratch (__device__ globals; no dynamic alloc) ----------------
__device__ int      g_cnt_dst1[NN];
__device__ int      g_off1[NN];
__device__ int      g_cur1[NN];
__device__ float4   g_ep1[E1];      // per-edge payload: {src, ea0, ea1, ea2}
__device__ int      g_cnt_c1[C1N];
__device__ int      g_cnt_dst2[C1N];
__device__ int      g_off2[C1N];
__device__ int      g_cur2[C1N];
__device__ float4   g_ep2[E2N];     // per-edge payload: {src, cart0, cart1, cart2}
__device__ float    g_possum[C1N * 3];
__device__ int      g_batchp[C1N];
__device__ unsigned g_xp_u[C1N * 32];
__device__ float    g_W1p[162 * 32];
__device__ unsigned g_absmax;
__device__ float    g_A2[C1N * 864];
__device__ float    g_W2p[864 * 64];
__device__ unsigned g_x3_u[C2N * 64];
__device__ int      g_batch2[C2N];
__device__ float    g_gsum[NBAT * 64];
__device__ int      g_cntb[NBAT];
__device__ unsigned g_alloc1;
__device__ unsigned g_alloc2;
__device__ unsigned g_bcnt = 0;
__device__ unsigned g_bgen = 0;

// ---------------- grid-wide barrier (all NB blocks resident by construction) ----------------
__device__ __forceinline__ void gsync() {
    __syncthreads();
    if (threadIdx.x == 0) {
        __threadfence();                                   // release: flush my writes
        unsigned gen = atomicAdd(&g_bgen, 0u);             // L2 read of current generation
        if (atomicAdd(&g_bcnt, 1u) == (unsigned)(gridDim.x - 1)) {
            atomicExch(&g_bcnt, 0u);
            atomicExch(&g_bgen, gen + 1u);                 // release all
        } else {
            while (atomicAdd(&g_bgen, 0u) == gen) { }      // spin via L2
        }
        __threadfence();                                   // acquire: invalidate L1
    }
    __syncthreads();
}

// packed f32x2 helpers (FFMA2 path — PTX-only, doubles fp32 FMA throughput)
__device__ __forceinline__ u64 pk(float lo, float hi) {
    u64 r; asm("mov.b64 %0,{%1,%2};" : "=l"(r) : "f"(lo), "f"(hi)); return r;
}
__device__ __forceinline__ void upk(u64 v, float& lo, float& hi) {
    asm("mov.b64 {%0,%1},%2;" : "=f"(lo), "=f"(hi) : "l"(v));
}
__device__ __forceinline__ u64 fma2(u64 a, u64 b, u64 c) {
    u64 d; asm("fma.rn.f32x2 %0,%1,%2,%3;" : "=l"(d) : "l"(a), "l"(b), "l"(c)); return d;
}

// order-preserving float <-> uint so atomicMax works; 0u == "empty" decodes to 0.0f
__device__ __forceinline__ unsigned fenc(float f) {
    unsigned u = __float_as_uint(f);
    return (u & 0x80000000u) ? ~u : (u | 0x80000000u);
}
__device__ __forceinline__ float fdec(unsigned u) {
    if (u == 0u) return 0.f;
    return (u & 0x80000000u) ? __uint_as_float(u & 0x7FFFFFFFu) : __uint_as_float(~u);
}
__device__ __forceinline__ float elu_f(float x) {
    return x > 0.f ? x : (expf(x) - 1.f);
}

// shared-memory overlay for the phases that need it
struct SG2 { u64 A[64][48]; float W[48][64]; };                       // 36864 B
struct SHD { float sg[16 * 64]; float sh[16 * 128]; float sl[160]; }; // 12928 B
struct SP2 { float sp[NBAT * 64]; int sc[NBAT]; };                    //  4160 B
union SMEM { SG2 g2; SHD hd; SP2 p2; };

// =====================================================================================
// ONE persistent kernel: 9 phases separated by grid barriers (no inter-kernel gaps)
// =====================================================================================
__global__ void __launch_bounds__(256, 4) k_all(
    const float* __restrict__ x, const float* __restrict__ ea, const float* __restrict__ pos,
    const int* __restrict__ eidx, const int* __restrict__ batch, const int* __restrict__ cl1,
    const int* __restrict__ eidx2, const int* __restrict__ cl2,
    const float* __restrict__ w1a, const float* __restrict__ b1a,
    const float* __restrict__ w1b, const float* __restrict__ b1b,
    const float* __restrict__ root1, const float* __restrict__ bias1,
    const float* __restrict__ w2a, const float* __restrict__ b2a,
    const float* __restrict__ w2b, const float* __restrict__ b2b,
    const float* __restrict__ root2, const float* __restrict__ bias2,
    const float* __restrict__ fc1w, const float* __restrict__ fc1b,
    const float* __restrict__ fc2w, const float* __restrict__ fc2b,
    float* __restrict__ out)
{
    __shared__ SMEM sm;
    const int tid  = threadIdx.x;
    const int g    = blockIdx.x * 256 + tid;
    const int TS   = NB * 256;               // total threads
    const int gw   = g >> 5;                 // global warp id
    const int GW   = NB * 8;                 // total warps
    const int lane = tid & 31;

    // ---------------- P0: zero scratch + repack fused weights ----------------
    for (int i = g; i < C1N * 32; i += TS) g_xp_u[i] = 0u;
    for (int i = g; i < C2N * 64; i += TS) g_x3_u[i] = 0u;
    for (int i = g; i < C1N * 3;  i += TS) g_possum[i] = 0.f;
    for (int i = g; i < NN;       i += TS) g_cnt_dst1[i] = 0;
    for (int i = g; i < C1N;      i += TS) { g_cnt_c1[i] = 0; g_cnt_dst2[i] = 0; g_batchp[i] = 0; }
    for (int i = g; i < C2N;      i += TS) g_batch2[i] = 0;
    for (int i = g; i < NBAT * 64; i += TS) g_gsum[i] = 0.f;
    for (int i = g; i < NBAT;     i += TS) g_cntb[i] = 0;
    if (g == 0) { g_absmax = 0u; g_alloc1 = 0u; g_alloc2 = 0u; }
    // W1p[j,o]: j=i*26+k (i<6,k<26): k<25 -> w1b[k, i*32+o], k==25 -> b1b[i*32+o];
    //           j in [156,162): root1[j-156, o]
    for (int idx = g; idx < 162 * 32; idx += TS) {
        int j = idx >> 5, o = idx & 31;
        float v;
        if (j < 156) {
            int i = j / 26, k = j % 26;
            v = (k < 25) ? w1b[k * 192 + i * 32 + o] : b1b[i * 32 + o];
        } else {
            v = root1[(j - 156) * 32 + o];
        }
        g_W1p[idx] = v;
    }
    // W2p[j,o]: j=k*32+i (k<26,i<32): k<25 -> w2b[k, i*64+o], k==25 -> b2b[i*64+o];
    //           j in [832,864): root2[j-832, o]
    for (int idx = g; idx < 864 * 64; idx += TS) {
        int j = idx >> 6, o = idx & 63;
        float v;
        if (j < 832) {
            int k = j >> 5, i = j & 31;
            v = (k < 25) ? w2b[k * 2048 + i * 64 + o] : b2b[i * 64 + o];
        } else {
            v = root2[(j - 832) * 64 + o];
        }
        g_W2p[idx] = v;
    }
    gsync();

    // ---------------- P1: degree counts + pos-sum + batchp ----------------
    for (int e = g; e < E1;  e += TS) atomicAdd(&g_cnt_dst1[eidx[E1 + e]], 1);
    for (int e = g; e < E2N; e += TS) atomicAdd(&g_cnt_dst2[eidx2[E2N + e]], 1);
    for (int n = g; n < NN;  n += TS) {
        int c = cl1[n];
        atomicAdd(&g_cnt_c1[c], 1);
        atomicAdd(&g_possum[c * 3 + 0], pos[n * 3 + 0]);
        atomicAdd(&g_possum[c * 3 + 1], pos[n * 3 + 1]);
        atomicAdd(&g_possum[c * 3 + 2], pos[n * 3 + 2]);
        atomicMax(&g_batchp[c], batch[n]);
    }
    gsync();

    // ---------------- P2: segment allocation (scan-free CSR offsets) + pos mean + batch2 ----
    for (int n = g; n < NN; n += TS) {
        int c = g_cnt_dst1[n];
        unsigned o = atomicAdd(&g_alloc1, (unsigned)c);
        g_off1[n] = (int)o; g_cur1[n] = (int)o;
    }
    for (int c = g; c < C1N; c += TS) {
        int cc = g_cnt_dst2[c];
        unsigned o = atomicAdd(&g_alloc2, (unsigned)cc);
        g_off2[c] = (int)o; g_cur2[c] = (int)o;
        float inv = 1.f / (float)max(g_cnt_c1[c], 1);
        g_possum[c * 3 + 0] *= inv;
        g_possum[c * 3 + 1] *= inv;
        g_possum[c * 3 + 2] *= inv;
        atomicMax(&g_batch2[cl2[c]], g_batchp[c]);
    }
    gsync();

    // ---------------- P3: fill CSR edge payloads (+ cartesian + absmax) ----------------
    for (int e = g; e < E1; e += TS) {
        int s = eidx[e], d = eidx[E1 + e];
        int p = atomicAdd(&g_cur1[d], 1);
        g_ep1[p] = make_float4(__int_as_float(s), ea[e * 3 + 0], ea[e * 3 + 1], ea[e * 3 + 2]);
    }
    {
        float m = 0.f;
        for (int e = g; e < E2N; e += TS) {
            int s = eidx2[e], d = eidx2[E2N + e];
            float c0 = g_possum[s * 3 + 0] - g_possum[d * 3 + 0];
            float c1 = g_possum[s * 3 + 1] - g_possum[d * 3 + 1];
            float c2 = g_possum[s * 3 + 2] - g_possum[d * 3 + 2];
            int p = atomicAdd(&g_cur2[d], 1);
            g_ep2[p] = make_float4(__int_as_float(s), c0, c1, c2);
            m = fmaxf(m, fmaxf(fabsf(c0), fmaxf(fabsf(c1), fabsf(c2))));
        }
#pragma unroll
        for (int o = 16; o; o >>= 1) m = fmaxf(m, __shfl_xor_sync(0xffffffffu, m, o));
        if (lane == 0 && m > 0.f) atomicMax(&g_absmax, __float_as_uint(m));
    }
    gsync();

    // ---------------- P4: conv1 + gemm1 + elu + pool1-max (one warp per dst node) ----------
    {
        float wa0 = 0.f, wa1 = 0.f, wa2 = 0.f, ba = 0.f;
        if (lane < 25) { wa0 = w1a[lane]; wa1 = w1a[25 + lane]; wa2 = w1a[50 + lane]; ba = b1a[lane]; }
        float bs1 = bias1[lane];
        for (int n = gw; n < NN; n += GW) {
            u64 acc0 = 0, acc1 = 0, acc2 = 0;
            int off = g_off1[n], deg = g_cnt_dst1[n];
            const float4* ep = &g_ep1[off];
            for (int q = 0; q < deg; q++) {
                float4 p = ep[q];                       // uniform broadcast load
                int s = __float_as_int(p.x);
                float h;
                if (lane < 25) {
                    h = fmaf(p.w, wa2, fmaf(p.z, wa1, fmaf(p.y, wa0, ba)));
                    h = fmaxf(h, 0.f);
                } else {
                    h = (lane == 25) ? 1.f : 0.f;
                }
                u64 hh = pk(h, h);
                const u64* xr = (const u64*)(x + s * 6);  // uniform broadcast, 8B-aligned
                acc0 = fma2(xr[0], hh, acc0);
                acc1 = fma2(xr[1], hh, acc1);
                acc2 = fma2(xr[2], hh, acc2);
            }
            float inv = 1.f / (float)max(deg, 1);
            float sv[6];
            upk(acc0, sv[0], sv[1]); upk(acc1, sv[2], sv[3]); upk(acc2, sv[4], sv[5]);
#pragma unroll
            for (int i = 0; i < 6; i++) sv[i] *= inv;
            float o_acc = bs1;
#pragma unroll
            for (int i = 0; i < 6; i++) {
                float si = sv[i];
#pragma unroll
                for (int k = 0; k < 26; k++) {
                    float av = __shfl_sync(0xffffffffu, si, k);
                    o_acc = fmaf(av, g_W1p[(i * 26 + k) * 32 + lane], o_acc);
                }
            }
            const u64* xs = (const u64*)(x + n * 6);
            float x0, x1, x2, x3, x4, x5;
            upk(xs[0], x0, x1); upk(xs[1], x2, x3); upk(xs[2], x4, x5);
            o_acc = fmaf(x0, g_W1p[156 * 32 + lane], o_acc);
            o_acc = fmaf(x1, g_W1p[157 * 32 + lane], o_acc);
            o_acc = fmaf(x2, g_W1p[158 * 32 + lane], o_acc);
            o_acc = fmaf(x3, g_W1p[159 * 32 + lane], o_acc);
            o_acc = fmaf(x4, g_W1p[160 * 32 + lane], o_acc);
            o_acc = fmaf(x5, g_W1p[161 * 32 + lane], o_acc);
            float v = elu_f(o_acc);
            atomicMax(&g_xp_u[cl1[n] * 32 + lane], fenc(v));
        }
    }
    gsync();

    // ---------------- P5: conv2 (one warp per dst cluster, inline xp decode) ----------------
    {
        float wa0 = 0.f, wa1 = 0.f, wa2 = 0.f, ba = 0.f;
        if (lane < 25) { wa0 = w2a[lane]; wa1 = w2a[25 + lane]; wa2 = w2a[50 + lane]; ba = b2a[lane]; }
        float scale = 0.5f / __uint_as_float(g_absmax);
        for (int c = gw; c < C1N; c += GW) {
            float acc[26];
#pragma unroll
            for (int k = 0; k < 26; k++) acc[k] = 0.f;
            int off = g_off2[c], deg = g_cnt_dst2[c];
            const float4* ep = &g_ep2[off];
            for (int q = 0; q < deg; q++) {
                float4 p = ep[q];
                int s = __float_as_int(p.x);
                float h;
                if (lane < 25) {
                    float c0 = fmaf(p.y, scale, 0.5f);
                    float c1 = fmaf(p.z, scale, 0.5f);
                    float c2 = fmaf(p.w, scale, 0.5f);
                    h = fmaf(c2, wa2, fmaf(c1, wa1, fmaf(c0, wa0, ba)));
                    h = fmaxf(h, 0.f);
                } else {
                    h = (lane == 25) ? 1.f : 0.f;
                }
                float xv = fdec(g_xp_u[s * 32 + lane]);  // coalesced 128B + inline decode
#pragma unroll
                for (int k = 0; k < 26; k++)
                    acc[k] = fmaf(xv, __shfl_sync(0xffffffffu, h, k), acc[k]);
            }
            float inv = 1.f / (float)max(deg, 1);
            float* Arow = &g_A2[c * 864];
#pragma unroll
            for (int k = 0; k < 26; k++) Arow[k * 32 + lane] = acc[k] * inv;
            Arow[832 + lane] = fdec(g_xp_u[c * 32 + lane]);
        }
    }
    gsync();

    // ---------------- P6: GEMM2 [C1,864]@[864,64] smem-tiled FFMA2 + elu + pool2-max -------
    {
        const int warp = tid >> 5;
        float b0 = bias2[2 * lane], b1 = bias2[2 * lane + 1];
        for (int tile = blockIdx.x; tile * 64 < C1N; tile += NB) {
            int row0 = tile * 64;
            u64 acc[8];
#pragma unroll
            for (int r = 0; r < 8; r++) acc[r] = 0;
            for (int kc = 0; kc < 864; kc += 48) {
                for (int i = tid; i < 64 * 48; i += 256) {
                    int r = i / 48, k = i - r * 48;
                    int rr = min(row0 + r, C1N - 1);
                    float v = g_A2[rr * 864 + kc + k];
                    sm.g2.A[r][k] = pk(v, v);
                }
                for (int i = tid; i < 48 * 64; i += 256)
                    sm.g2.W[i >> 6][i & 63] = g_W2p[(kc + (i >> 6)) * 64 + (i & 63)];
                __syncthreads();
                int rb = warp * 8;
#pragma unroll 4
                for (int k = 0; k < 48; k++) {
                    u64 w = *(const u64*)&sm.g2.W[k][2 * lane];
#pragma unroll
                    for (int r = 0; r < 8; r++)
                        acc[r] = fma2(sm.g2.A[rb + r][k], w, acc[r]);
                }
                __syncthreads();
            }
#pragma unroll
            for (int r = 0; r < 8; r++) {
                int n = row0 + warp * 8 + r;
                if (n < C1N) {
                    float a0, a1;
                    upk(acc[r], a0, a1);
                    float v0 = elu_f(a0 + b0);
                    float v1 = elu_f(a1 + b1);
                    int c2 = cl2[n];
                    atomicMax(&g_x3_u[c2 * 64 + 2 * lane + 0], fenc(v0));
                    atomicMax(&g_x3_u[c2 * 64 + 2 * lane + 1], fenc(v1));
                }
            }
        }
    }
    gsync();

    // ---------------- P7: pool2 -> per-batch sums via shared staging ----------------
    {
        for (int i = tid; i < NBAT * 64; i += 256) sm.p2.sp[i] = 0.f;
        if (tid < NBAT) sm.p2.sc[tid] = 0;
        __syncthreads();
        for (int idx = g; idx < C2N * 64; idx += TS) {
            float v = fdec(g_x3_u[idx]);
            int c2 = idx >> 6, o = idx & 63;
            int b = g_batch2[c2];
            atomicAdd(&sm.p2.sp[b * 64 + o], v);
            if (o == 0) atomicAdd(&sm.p2.sc[b], 1);
        }
        __syncthreads();
        for (int i = tid; i < NBAT * 64; i += 256)
            if (sm.p2.sp[i] != 0.f) atomicAdd(&g_gsum[i], sm.p2.sp[i]);
        if (tid < NBAT && sm.p2.sc[tid]) atomicAdd(&g_cntb[tid], sm.p2.sc[tid]);
    }
    gsync();

    // ---------------- P8: head (block 0): mean -> fc1+elu -> fc2 -> log_softmax ------------
    if (blockIdx.x == 0) {
        __syncthreads();
        for (int i = tid; i < 16 * 64; i += 256) {
            int b = i >> 6;
            sm.hd.sg[i] = g_gsum[i] / (float)max(g_cntb[b], 1);
        }
        __syncthreads();
        for (int i = tid; i < 16 * 128; i += 256) {
            int b = i >> 7, j = i & 127;
            float a = fc1b[j];
            for (int q = 0; q < 64; q++) a = fmaf(sm.hd.sg[b * 64 + q], fc1w[q * 128 + j], a);
            sm.hd.sh[i] = elu_f(a);
        }
        __syncthreads();
        for (int i = tid; i < 160; i += 256) {
            int b = i / 10, j = i % 10;
            float a = fc2b[j];
            for (int q = 0; q < 128; q++) a = fmaf(sm.hd.sh[b * 128 + q], fc2w[q * 10 + j], a);
            sm.hd.sl[i] = a;
        }
        __syncthreads();
        if (tid < 16) {
            float m = -1e30f;
            for (int j = 0; j < 10; j++) m = fmaxf(m, sm.hd.sl[tid * 10 + j]);
            float s = 0.f;
            for (int j = 0; j < 10; j++) s += expf(sm.hd.sl[tid * 10 + j] - m);
            float lse = logf(s);
            for (int j = 0; j < 10; j++) out[tid * 10 + j] = sm.hd.sl[tid * 10 + j] - m - lse;
        }
    }
}

// ---------------- host launch: ONE kernel ----------------
extern "C" void kernel_launch(void* const* d_in, const int* in_sizes, int n_in,
                              void* d_out, int out_size) {
    const float *x = 0, *ea = 0, *pos = 0, *w1a = 0, *b1a = 0, *w1b = 0, *b1b = 0,
                *root1 = 0, *bias1 = 0, *w2a = 0, *b2a = 0, *w2b = 0, *b2b = 0,
                *root2 = 0, *bias2 = 0, *fc1w = 0, *fc1b = 0, *fc2w = 0, *fc2b = 0;
    const int *eidx = 0, *batch = 0, *cl1 = 0, *eidx2 = 0, *cl2 = 0;
    int c75 = 0, c25 = 0, c192 = 0, c2048 = 0, c30000 = 0;
    for (int i = 0; i < n_in; i++) {
        const void* p = d_in[i];
        switch (in_sizes[i]) {
            case 180000:  x = (const float*)p; break;
            case 1200000: ea = (const float*)p; break;
            case 90000:   pos = (const float*)p; break;
            case 800000:  eidx = (const int*)p; break;
            case 30000:   if (c30000++ == 0) batch = (const int*)p; else cl1 = (const int*)p; break;
            case 200000:  eidx2 = (const int*)p; break;
            case 15000:   cl2 = (const int*)p; break;
            case 75:      if (c75++ == 0) w1a = (const float*)p; else w2a = (const float*)p; break;
            case 25:      if (c25++ == 0) b1a = (const float*)p; else b2a = (const float*)p; break;
            case 4800:    w1b = (const float*)p; break;
            case 192:     if (c192++ == 0) b1b = (const float*)p; else root1 = (const float*)p; break;
            case 32:      bias1 = (const float*)p; break;
            case 51200:   w2b = (const float*)p; break;
            case 2048:    if (c2048++ == 0) b2b = (const float*)p; else root2 = (const float*)p; break;
            case 64:      bias2 = (const float*)p; break;
            case 8192:    fc1w = (const float*)p; break;
            case 128:     fc1b = (const float*)p; break;
            case 1280:    fc2w = (const float*)p; break;
            case 10:      fc2b = (const float*)p; break;
            default: break;
        }
    }
    float* out = (float*)d_out;
    (void)out_size;

    k_all<<<NB, 256>>>(x, ea, pos, eidx, batch, cl1, eidx2, cl2,
                       w1a, b1a, w1b, b1b, root1, bias1,
                       w2a, b2a, w2b, b2b, root2, bias2,
                       fc1w, fc1b, fc2w, fc2b, out);
}